// round 2
// baseline (speedup 1.0000x reference)
#include <cuda_runtime.h>

// Per-position head-mixing attention, one CTA (128 thr) per position.
// Lane mapping (per warp, heads h0..h0+7):
//   hsel = lane&3  -> lane owns heads h0+hsel and h0+4+hsel
//   gsel = lane>>2 -> lane owns score columns g = gsel + 8j (j=0..3)
// Phase 1: S[h][g] = Q[h]·K[g]/sqrt(D). Q read from GLOBAL (4-chunk multicast
// LDG, each warp reads only its own 8 rows). K read from smem with XOR swizzle
// so each LDS delivers 128B of distinct data (8 rows x 16B, 4-way multicast).
// Softmax over g: 4 local regs + shfl_xor(4,8,16) across the 8 g-owner lanes.
// Phase 2: O[h][gsel+8m] += P[h][g] * V[g][gsel+8m]; P broadcast via 2 shfl/g,
// V rows read from smem conflict-free (8 distinct chunks, no swizzle needed).
// All FMAs are packed fma.rn.f32x2.

constexpr int HEADS = 32;
constexpr int DIM   = 128;
constexpr int ROW4  = DIM / 4;            // 32 float4 per row
constexpr int TILE4 = HEADS * ROW4;       // 1024 float4 per tile
constexpr int SMEM_BYTES = 2 * HEADS * DIM * 4;   // 32 KB: K + V

__device__ __forceinline__ unsigned long long pack2(float lo, float hi) {
    unsigned long long r;
    asm("mov.b64 %0, {%1, %2};" : "=l"(r) : "f"(lo), "f"(hi));
    return r;
}
__device__ __forceinline__ void unpack2(unsigned long long v, float& lo, float& hi) {
    asm("mov.b64 {%0, %1}, %2;" : "=f"(lo), "=f"(hi) : "l"(v));
}
__device__ __forceinline__ void fma2(unsigned long long& acc,
                                     unsigned long long a, unsigned long long b) {
    asm("fma.rn.f32x2 %0, %1, %2, %0;" : "+l"(acc) : "l"(a), "l"(b));
}

__global__ void __launch_bounds__(128)
attn_kernel(const float* __restrict__ Q, const float* __restrict__ K,
            const float* __restrict__ V, float* __restrict__ O) {
    extern __shared__ float smem[];
    float4* Ks4 = reinterpret_cast<float4*>(smem);            // XOR-swizzled
    float4* Vs4 = Ks4 + TILE4;                                // plain layout

    const int pos = blockIdx.x;
    const long long base4 = (long long)pos * TILE4;
    const float4* Qg = reinterpret_cast<const float4*>(Q) + base4;
    const float4* Kg = reinterpret_cast<const float4*>(K) + base4;
    const float4* Vg = reinterpret_cast<const float4*>(V) + base4;

    const int tid  = threadIdx.x;
    const int lane = tid & 31;
    const int h0   = (tid >> 5) * 8;
    const int hsel = lane & 3;
    const int gsel = lane >> 2;    // 0..7

    // ---- stage K (swizzled) and V (plain) into smem; Q never staged ----
    #pragma unroll
    for (int j = 0; j < 8; ++j) {
        int i = j * 128 + tid;
        int r = i >> 5, p = i & 31;
        Ks4[r * ROW4 + (p ^ (r & 7))] = Kg[i];   // XOR swizzle on chunk bits
        Vs4[i] = Vg[i];
    }
    __syncthreads();

    // ---- phase 1: scores ----
    unsigned long long acc0[4], acc1[4];
    #pragma unroll
    for (int j = 0; j < 4; ++j) { acc0[j] = 0ULL; acc1[j] = 0ULL; }

    const float4* Qrow0 = Qg + (h0 + hsel) * ROW4;
    const float4* Qrow1 = Qg + (h0 + 4 + hsel) * ROW4;

    #pragma unroll 8
    for (int p = 0; p < 32; ++p) {
        float4 q0 = Qrow0[p];                    // LDG: 4 chunks x 8-way mcast
        float4 q1 = Qrow1[p];
        unsigned long long q0a = pack2(q0.x, q0.y), q0b = pack2(q0.z, q0.w);
        unsigned long long q1a = pack2(q1.x, q1.y), q1b = pack2(q1.z, q1.w);
        int pc = p ^ gsel;                       // (r&7)==gsel for all j
        #pragma unroll
        for (int j = 0; j < 4; ++j) {
            int r = gsel + 8 * j;
            float4 k = Ks4[r * ROW4 + pc];       // 8 rows x 16B = 128B dense
            unsigned long long ka = pack2(k.x, k.y), kb = pack2(k.z, k.w);
            fma2(acc0[j], q0a, ka); fma2(acc0[j], q0b, kb);
            fma2(acc1[j], q1a, ka); fma2(acc1[j], q1b, kb);
        }
    }

    // ---- softmax over g (4 local values + 8 lanes via shfl_xor 4,8,16) ----
    const float scale = 0.0883883476483184405f;  // 1/sqrt(128)
    float e0[4], e1[4];
    {
        float s0[4], s1[4];
        #pragma unroll
        for (int j = 0; j < 4; ++j) {
            float lo, hi;
            unpack2(acc0[j], lo, hi); s0[j] = (lo + hi) * scale;
            unpack2(acc1[j], lo, hi); s1[j] = (lo + hi) * scale;
        }
        float m0 = fmaxf(fmaxf(s0[0], s0[1]), fmaxf(s0[2], s0[3]));
        float m1 = fmaxf(fmaxf(s1[0], s1[1]), fmaxf(s1[2], s1[3]));
        #pragma unroll
        for (int off = 4; off <= 16; off <<= 1) {
            m0 = fmaxf(m0, __shfl_xor_sync(0xffffffffu, m0, off));
            m1 = fmaxf(m1, __shfl_xor_sync(0xffffffffu, m1, off));
        }
        float sum0 = 0.f, sum1 = 0.f;
        #pragma unroll
        for (int j = 0; j < 4; ++j) {
            e0[j] = __expf(s0[j] - m0); sum0 += e0[j];
            e1[j] = __expf(s1[j] - m1); sum1 += e1[j];
        }
        #pragma unroll
        for (int off = 4; off <= 16; off <<= 1) {
            sum0 += __shfl_xor_sync(0xffffffffu, sum0, off);
            sum1 += __shfl_xor_sync(0xffffffffu, sum1, off);
        }
        float r0 = 1.0f / sum0, r1 = 1.0f / sum1;
        #pragma unroll
        for (int j = 0; j < 4; ++j) { e0[j] *= r0; e1[j] *= r1; }  // pre-normalize
    }

    // ---- phase 2: O[h][gsel+8m] = sum_g P[h][g] V[g][gsel+8m] ----
    unsigned long long oa0[4], ob0[4], oa1[4], ob1[4];  // [m], halves a/b
    #pragma unroll
    for (int m = 0; m < 4; ++m) { oa0[m]=0ULL; ob0[m]=0ULL; oa1[m]=0ULL; ob1[m]=0ULL; }

    #pragma unroll
    for (int j = 0; j < 4; ++j) {
        #pragma unroll
        for (int gg = 0; gg < 8; ++gg) {
            const int g = 8 * j + gg;
            const int srcl = hsel + 4 * gg;          // lane holding P[h][g]
            float p0 = __shfl_sync(0xffffffffu, e0[j], srcl);
            float p1 = __shfl_sync(0xffffffffu, e1[j], srcl);
            unsigned long long p0x = pack2(p0, p0);
            unsigned long long p1x = pack2(p1, p1);
            const float4* vrow = Vs4 + g * ROW4 + gsel;
            #pragma unroll
            for (int m = 0; m < 4; ++m) {
                float4 v = vrow[8 * m];              // 8 chunks x 16B dense
                unsigned long long va = pack2(v.x, v.y), vb = pack2(v.z, v.w);
                fma2(oa0[m], p0x, va); fma2(ob0[m], p0x, vb);
                fma2(oa1[m], p1x, va); fma2(ob1[m], p1x, vb);
            }
        }
    }

    // ---- store (coalesced 128B groups per head row) ----
    float4* Og = reinterpret_cast<float4*>(O) + base4;
    float4* Orow0 = Og + (h0 + hsel) * ROW4 + gsel;
    float4* Orow1 = Og + (h0 + 4 + hsel) * ROW4 + gsel;
    #pragma unroll
    for (int m = 0; m < 4; ++m) {
        float a, b, c, d;
        unpack2(oa0[m], a, b); unpack2(ob0[m], c, d);
        Orow0[8 * m] = make_float4(a, b, c, d);
        unpack2(oa1[m], a, b); unpack2(ob1[m], c, d);
        Orow1[8 * m] = make_float4(a, b, c, d);
    }
}

extern "C" void kernel_launch(void* const* d_in, const int* in_sizes, int n_in,
                              void* d_out, int out_size) {
    const float* Q = (const float*)d_in[0];
    const float* K = (const float*)d_in[1];
    const float* V = (const float*)d_in[2];
    float* O = (float*)d_out;
    int positions = in_sizes[0] / (HEADS * DIM);   // B*N = 16384
    cudaFuncSetAttribute(attn_kernel,
                         cudaFuncAttributeMaxDynamicSharedMemorySize, SMEM_BYTES);
    attn_kernel<<<positions, 128, SMEM_BYTES>>>(Q, K, V, O);
}

// round 3
// speedup vs baseline: 1.9203x; 1.9203x over previous
#include <cuda_runtime.h>
#include <cstdint>

// Per-position head-mixing attention; 1 CTA (128 thr) per position.
// Lane map: gsel = lane&7 (owns score cols g = gsel+8j, j=0..3),
//           psel = lane>>3 (owns dim chunks c = psel+4m, m=0..7).
// Phase 1: partial S[h][g] over lane's 8 chunks; reduce over psel (shfl 8,16);
//          softmax over g (shfl 1,2,4). Q LDS = 64B-multicast, K LDS dense
//          (XOR swizzle). Q/V tiles arrive via cp.async.bulk (no warp ops).
// P staged to smem transposed [g][h] -> phase 2 reads 2 broadcast LDS.128/g.
// Phase 2: O[h][chunk=lane] += P[h][g]*V[g][chunk], V reads dense.
// All FMAs packed fma.rn.f32x2.

constexpr int HEADS = 32;
constexpr int DIM   = 128;
constexpr int ROW4  = DIM / 4;            // 32
constexpr int TILE4 = HEADS * ROW4;       // 1024 float4
constexpr int TILE_BYTES = HEADS * DIM * 4;         // 16384
// smem floats: K[4096] V[4096] Q[4096] P[4*32*8=1024] + 2 mbarriers
constexpr int SMEM_BYTES = 3 * TILE_BYTES + 4096 + 16;

__device__ __forceinline__ unsigned long long pack2(float lo, float hi) {
    unsigned long long r;
    asm("mov.b64 %0, {%1, %2};" : "=l"(r) : "f"(lo), "f"(hi));
    return r;
}
__device__ __forceinline__ void unpack2(unsigned long long v, float& lo, float& hi) {
    asm("mov.b64 {%0, %1}, %2;" : "=f"(lo), "=f"(hi) : "l"(v));
}
__device__ __forceinline__ void fma2(unsigned long long& acc,
                                     unsigned long long a, unsigned long long b) {
    asm("fma.rn.f32x2 %0, %1, %2, %0;" : "+l"(acc) : "l"(a), "l"(b));
}
__device__ __forceinline__ uint32_t s2u(const void* p) {
    uint32_t a;
    asm("{ .reg .u64 t; cvta.to.shared.u64 t, %1; cvt.u32.u64 %0, t; }"
        : "=r"(a) : "l"(p));
    return a;
}
__device__ __forceinline__ void mbar_init(uint32_t a) {
    asm volatile("mbarrier.init.shared::cta.b64 [%0], 1;" :: "r"(a) : "memory");
}
__device__ __forceinline__ void mbar_expect(uint32_t a, uint32_t bytes) {
    asm volatile("mbarrier.arrive.expect_tx.shared::cta.b64 _, [%0], %1;"
                 :: "r"(a), "r"(bytes) : "memory");
}
__device__ __forceinline__ void bulk_g2s(uint32_t dst, const void* src,
                                         uint32_t bytes, uint32_t mbar) {
    asm volatile("cp.async.bulk.shared::cta.global.mbarrier::complete_tx::bytes "
                 "[%0], [%1], %2, [%3];"
                 :: "r"(dst), "l"(src), "r"(bytes), "r"(mbar) : "memory");
}
__device__ __forceinline__ void mbar_wait0(uint32_t a) {
    asm volatile(
        "{\n\t.reg .pred P;\n"
        "W%=:\n\tmbarrier.try_wait.parity.acquire.cta.shared::cta.b64 P, [%0], 0;\n"
        "\t@P bra D%=;\n\tbra W%=;\nD%=:\n\t}"
        :: "r"(a) : "memory");
}

__global__ void __launch_bounds__(128, 4)
attn_kernel(const float* __restrict__ Q, const float* __restrict__ K,
            const float* __restrict__ V, float* __restrict__ O) {
    extern __shared__ float smem[];
    float4* Ks4 = reinterpret_cast<float4*>(smem);          // XOR-swizzled
    float4* Vs4 = Ks4 + TILE4;                              // plain (bulk)
    float4* Qs4 = Vs4 + TILE4;                              // plain (bulk)
    float*  Pw  = smem + 3 * (TILE4 * 4);                   // [4][32][8]
    uint64_t* mbars = reinterpret_cast<uint64_t*>(Pw + 1024);

    const int pos = blockIdx.x;
    const long long base4 = (long long)pos * TILE4;
    const float4* Kg = reinterpret_cast<const float4*>(K) + base4;

    const int tid  = threadIdx.x;
    const int lane = tid & 31;
    const int w    = tid >> 5;
    const int h0   = w * 8;
    const int gsel = lane & 7;
    const int psel = lane >> 3;

    const uint32_t mbQ = s2u(&mbars[0]);
    const uint32_t mbV = s2u(&mbars[1]);

    if (tid == 0) { mbar_init(mbQ); mbar_init(mbV); }
    __syncthreads();
    if (tid == 0) {
        mbar_expect(mbQ, TILE_BYTES);
        bulk_g2s(s2u(Qs4), Q + (long long)pos * HEADS * DIM, TILE_BYTES, mbQ);
        mbar_expect(mbV, TILE_BYTES);
        bulk_g2s(s2u(Vs4), V + (long long)pos * HEADS * DIM, TILE_BYTES, mbV);
    }

    // ---- stage K with XOR swizzle (only array needing a layout change) ----
    #pragma unroll
    for (int j = 0; j < 8; ++j) {
        int i = j * 128 + tid;
        int r = i >> 5, c = i & 31;
        Ks4[r * ROW4 + (c ^ (r & 7))] = Kg[i];
    }
    __syncthreads();
    mbar_wait0(mbQ);     // Q tile ready

    // ---- phase 1: partial scores over lane's 8 chunks ----
    unsigned long long acc[8][4];
    #pragma unroll
    for (int h = 0; h < 8; ++h)
        #pragma unroll
        for (int j = 0; j < 4; ++j) acc[h][j] = 0ULL;

    #pragma unroll
    for (int m = 0; m < 8; ++m) {
        const int c = psel + 4 * m;
        unsigned long long ka[4], kb[4];
        #pragma unroll
        for (int j = 0; j < 4; ++j) {
            float4 k4 = Ks4[(gsel + 8 * j) * ROW4 + (c ^ gsel)];  // dense 4wf
            ka[j] = pack2(k4.x, k4.y);
            kb[j] = pack2(k4.z, k4.w);
        }
        #pragma unroll
        for (int h = 0; h < 8; ++h) {
            float4 q4 = Qs4[(h0 + h) * ROW4 + c];   // 4 chunks x 8-way mcast
            unsigned long long qa = pack2(q4.x, q4.y);
            unsigned long long qb = pack2(q4.z, q4.w);
            #pragma unroll
            for (int j = 0; j < 4; ++j) {
                fma2(acc[h][j], qa, ka[j]);
                fma2(acc[h][j], qb, kb[j]);
            }
        }
    }

    // ---- reduce over psel; softmax over g; write P^T to smem ----
    const float scale = 0.0883883476483184405f;    // 1/sqrt(128)
    float P_[8][4];
    #pragma unroll
    for (int h = 0; h < 8; ++h) {
        float s[4];
        #pragma unroll
        for (int j = 0; j < 4; ++j) {
            float lo, hi;
            unpack2(acc[h][j], lo, hi);
            float t = lo + hi;
            t += __shfl_xor_sync(0xffffffffu, t, 8);
            t += __shfl_xor_sync(0xffffffffu, t, 16);
            s[j] = t * scale;
        }
        float mx = fmaxf(fmaxf(s[0], s[1]), fmaxf(s[2], s[3]));
        #pragma unroll
        for (int off = 1; off <= 4; off <<= 1)
            mx = fmaxf(mx, __shfl_xor_sync(0xffffffffu, mx, off));
        float sum = 0.f;
        #pragma unroll
        for (int j = 0; j < 4; ++j) { P_[h][j] = __expf(s[j] - mx); sum += P_[h][j]; }
        #pragma unroll
        for (int off = 1; off <= 4; off <<= 1)
            sum += __shfl_xor_sync(0xffffffffu, sum, off);
        float r = 1.0f / sum;
        #pragma unroll
        for (int j = 0; j < 4; ++j) P_[h][j] *= r;
    }

    float* PwW = Pw + w * 256;          // this warp's [32][8]
    if (psel == 0) {                    // 8 lanes write 8 rows, compile-time h idx
        #pragma unroll
        for (int j = 0; j < 4; ++j) {
            int g = gsel + 8 * j;
            *reinterpret_cast<float4*>(&PwW[g * 8]) =
                make_float4(P_[0][j], P_[1][j], P_[2][j], P_[3][j]);
            *reinterpret_cast<float4*>(&PwW[g * 8 + 4]) =
                make_float4(P_[4][j], P_[5][j], P_[6][j], P_[7][j]);
        }
    }
    __syncwarp();
    mbar_wait0(mbV);     // V tile ready

    // ---- phase 2: O[h][chunk=lane] = sum_g P[h][g] * V[g][chunk] ----
    unsigned long long oa[8], ob[8];
    #pragma unroll
    for (int h = 0; h < 8; ++h) { oa[h] = 0ULL; ob[h] = 0ULL; }

    #pragma unroll 8
    for (int g = 0; g < 32; ++g) {
        float4 v4 = Vs4[g * ROW4 + lane];       // row g, 32 chunks dense
        unsigned long long va = pack2(v4.x, v4.y);
        unsigned long long vb = pack2(v4.z, v4.w);
        float4 pA = *reinterpret_cast<const float4*>(&PwW[g * 8]);      // bcast
        float4 pB = *reinterpret_cast<const float4*>(&PwW[g * 8 + 4]);  // bcast
        unsigned long long p0 = pack2(pA.x, pA.x), p1 = pack2(pA.y, pA.y);
        unsigned long long p2 = pack2(pA.z, pA.z), p3 = pack2(pA.w, pA.w);
        unsigned long long p4 = pack2(pB.x, pB.x), p5 = pack2(pB.y, pB.y);
        unsigned long long p6 = pack2(pB.z, pB.z), p7 = pack2(pB.w, pB.w);
        fma2(oa[0], p0, va); fma2(ob[0], p0, vb);
        fma2(oa[1], p1, va); fma2(ob[1], p1, vb);
        fma2(oa[2], p2, va); fma2(ob[2], p2, vb);
        fma2(oa[3], p3, va); fma2(ob[3], p3, vb);
        fma2(oa[4], p4, va); fma2(ob[4], p4, vb);
        fma2(oa[5], p5, va); fma2(ob[5], p5, vb);
        fma2(oa[6], p6, va); fma2(ob[6], p6, vb);
        fma2(oa[7], p7, va); fma2(ob[7], p7, vb);
    }

    // ---- store: per head row, lanes cover 32 chunks (coalesced) ----
    float4* Og = reinterpret_cast<float4*>(O) + base4;
    #pragma unroll
    for (int h = 0; h < 8; ++h) {
        float a, b, c, d;
        unpack2(oa[h], a, b);
        unpack2(ob[h], c, d);
        Og[(h0 + h) * ROW4 + lane] = make_float4(a, b, c, d);
    }
}

extern "C" void kernel_launch(void* const* d_in, const int* in_sizes, int n_in,
                              void* d_out, int out_size) {
    const float* Q = (const float*)d_in[0];
    const float* K = (const float*)d_in[1];
    const float* V = (const float*)d_in[2];
    float* O = (float*)d_out;
    int positions = in_sizes[0] / (HEADS * DIM);   // B*N = 16384
    cudaFuncSetAttribute(attn_kernel,
                         cudaFuncAttributeMaxDynamicSharedMemorySize, SMEM_BYTES);
    attn_kernel<<<positions, 128, SMEM_BYTES>>>(Q, K, V, O);
}